// round 14
// baseline (speedup 1.0000x reference)
#include <cuda_runtime.h>
#include <cuda_fp16.h>
#include <cstdint>

#define NN 50000
#define DF 256
#define NF 192
#define EF 64
#define ME 800000
#define OF 2048
#define NDEPTH 3

// static device scratch (no allocations anywhere)
__device__ float g_A[(size_t)NN * DF];
__device__ float g_L0[(size_t)NN * OF];
__device__ float g_L1[(size_t)NN * OF];
__device__ __half g_Ah[(size_t)NN * DF];
__device__ __half g_Al[(size_t)NN * DF];
__device__ __half g_Vh[(size_t)NN * DF];
__device__ __half g_Vl[(size_t)NN * DF];
#define WI_OFF ((size_t)4 * OF * DF)
__device__ __half g_Wth[WI_OFF + (size_t)NDEPTH * DF * DF];
__device__ __half g_Wtl[WI_OFF + (size_t)NDEPTH * DF * DF];
__device__ int g_deg[NN + 1];
__device__ int g_offs[NN + 1];
__device__ int g_cur[NN + 1];
__device__ int g_eidx[ME];

#define SASTR 40  // smem row stride in halfs (80 B): conflict-free frag lds + aligned cp.async

__device__ __forceinline__ uint32_t smem_u32(const void* p) {
    uint32_t a;
    asm("{ .reg .u64 t; cvta.to.shared.u64 t, %1; cvt.u32.u64 %0, t; }" : "=r"(a) : "l"(p));
    return a;
}
__device__ __forceinline__ void cpasync16(uint32_t dst, const void* src, int sz) {
    asm volatile("cp.async.cg.shared.global [%0], [%1], 16, %2;"
                 :: "r"(dst), "l"(src), "r"(sz) : "memory");
}
__device__ __forceinline__ void mma16816(float* c, const uint32_t* a, const uint32_t* b) {
    asm volatile(
        "mma.sync.aligned.m16n8k16.row.col.f32.f16.f16.f32 "
        "{%0,%1,%2,%3}, {%4,%5,%6,%7}, {%8,%9}, {%0,%1,%2,%3};"
        : "+f"(c[0]), "+f"(c[1]), "+f"(c[2]), "+f"(c[3])
        : "r"(a[0]), "r"(a[1]), "r"(a[2]), "r"(a[3]), "r"(b[0]), "r"(b[1]));
}

// CTA tile 256x128, BK=32, 256 threads, 8 warps (4 row x 2 col), warp tile 64x64.
#define STG_B 61440
#define GH_SMEM (2 * STG_B)  // 122880

__global__ __launch_bounds__(256, 1)
void gemm_h(const __half* __restrict__ Ahg, const __half* __restrict__ Alg,
            const __half* __restrict__ Bth, const __half* __restrict__ Btl,
            const float* __restrict__ bias, float* __restrict__ C, int M, int Ng,
            __half* __restrict__ Choh, __half* __restrict__ Chol, int nIter) {
    extern __shared__ __half sm[];
    uint32_t sb = smem_u32(sm);
    int tid = threadIdx.x, lane = tid & 31, wid = tid >> 5;
    int g = lane >> 2, t = lane & 3;
    int wm = (wid & 3) * 64, wn = (wid >> 2) * 64;
    int row0 = blockIdx.y * 256, col0 = blockIdx.x * 128;

    float acc[4][8][4];
#pragma unroll
    for (int i = 0; i < 4; i++)
#pragma unroll
        for (int j = 0; j < 8; j++)
#pragma unroll
            for (int k = 0; k < 4; k++) acc[i][j][k] = 0.f;

    auto issue = [&](int it) {
        int b = it & 1, k0 = it * 32;
        uint32_t bufb = sb + b * STG_B;
#pragma unroll
        for (int q = 0; q < 4; q++) {  // A: 256 rows x 4 chunks, hi+lo
            int idx = tid + q * 256;
            int r = idx >> 2, c4 = idx & 3;
            int rr = row0 + r;
            int p = (rr < M) ? 16 : 0;
            if (rr >= M) rr = M - 1;
            size_t so = (size_t)rr * DF + k0 + c4 * 8;
            uint32_t d = bufb + r * 80 + c4 * 16;
            cpasync16(d, Ahg + so, p);
            cpasync16(d + 20480, Alg + so, p);
        }
#pragma unroll
        for (int q = 0; q < 2; q++) {  // B: 128 rows x 4 chunks, hi+lo
            int idx = tid + q * 256;
            int n = idx >> 2, c4 = idx & 3;
            size_t so = (size_t)(col0 + n) * DF + k0 + c4 * 8;
            uint32_t d = bufb + 40960 + n * 80 + c4 * 16;
            cpasync16(d, Bth + so, 16);
            cpasync16(d + 10240, Btl + so, 16);
        }
        asm volatile("cp.async.commit_group;" ::: "memory");
    };

    auto compute = [&](int b) {
        const __half* Ahs = sm + b * (STG_B / 2);
        const __half* Als = Ahs + 10240;
        const __half* Bhs = Ahs + 20480;
        const __half* Bls = Ahs + 25600;
#pragma unroll
        for (int ks = 0; ks < 2; ks++) {
            uint32_t ah[4][4], al[4][4];
#pragma unroll
            for (int mt = 0; mt < 4; mt++) {
                int r = wm + mt * 16;
                int o0 = (r + g) * SASTR + ks * 16 + 2 * t;
                int o1 = (r + g + 8) * SASTR + ks * 16 + 2 * t;
                ah[mt][0] = *(const uint32_t*)&Ahs[o0];
                ah[mt][1] = *(const uint32_t*)&Ahs[o1];
                ah[mt][2] = *(const uint32_t*)&Ahs[o0 + 8];
                ah[mt][3] = *(const uint32_t*)&Ahs[o1 + 8];
                al[mt][0] = *(const uint32_t*)&Als[o0];
                al[mt][1] = *(const uint32_t*)&Als[o1];
                al[mt][2] = *(const uint32_t*)&Als[o0 + 8];
                al[mt][3] = *(const uint32_t*)&Als[o1 + 8];
            }
            uint32_t bh[8][2], bl[8][2];
#pragma unroll
            for (int nt = 0; nt < 8; nt++) {
                int ob = (wn + nt * 8 + g) * SASTR + ks * 16 + 2 * t;
                bh[nt][0] = *(const uint32_t*)&Bhs[ob];
                bh[nt][1] = *(const uint32_t*)&Bhs[ob + 8];
                bl[nt][0] = *(const uint32_t*)&Bls[ob];
                bl[nt][1] = *(const uint32_t*)&Bls[ob + 8];
            }
            // term-major: 3 passes of 32 independent MMAs (RAW distance 32)
#pragma unroll
            for (int nt = 0; nt < 8; nt++)
#pragma unroll
                for (int mt = 0; mt < 4; mt++)
                    mma16816(acc[mt][nt], ah[mt], bh[nt]);  // hi*hi
#pragma unroll
            for (int nt = 0; nt < 8; nt++)
#pragma unroll
                for (int mt = 0; mt < 4; mt++)
                    mma16816(acc[mt][nt], ah[mt], bl[nt]);  // hi*lo
#pragma unroll
            for (int nt = 0; nt < 8; nt++)
#pragma unroll
                for (int mt = 0; mt < 4; mt++)
                    mma16816(acc[mt][nt], al[mt], bh[nt]);  // lo*hi
        }
    };

    issue(0);
#pragma unroll 1
    for (int it = 0; it < nIter; it++) {
        asm volatile("cp.async.wait_group 0;" ::: "memory");
        __syncthreads();
        if (it + 1 < nIter) issue(it + 1);  // overlap next load with this compute
        compute(it & 1);
    }

#pragma unroll
    for (int mt = 0; mt < 4; mt++) {
#pragma unroll
        for (int i = 0; i < 2; i++) {
            int r = row0 + wm + mt * 16 + g + i * 8;
            if (r < M) {
#pragma unroll
                for (int nt = 0; nt < 8; nt++) {
                    int cc = col0 + wn + nt * 8 + 2 * t;
                    float2 v;
                    v.x = acc[mt][nt][i * 2 + 0] + bias[cc];
                    v.y = acc[mt][nt][i * 2 + 1] + bias[cc + 1];
                    *(float2*)&C[(size_t)r * Ng + cc] = v;
                    if (Choh) {
                        __half hx = __float2half_rn(v.x), hy = __float2half_rn(v.y);
                        *(__half2*)&Choh[(size_t)r * Ng + cc] = __halves2half2(hx, hy);
                        *(__half2*)&Chol[(size_t)r * Ng + cc] = __halves2half2(
                            __float2half_rn(v.x - __half2float(hx)),
                            __float2half_rn(v.y - __half2float(hy)));
                    }
                }
            }
        }
    }
}

// W [256, N] -> transposed hi/lo halves Wt[n][k] (K=256 row stride)
__global__ void wconvT(const float* __restrict__ W, __half* __restrict__ Th,
                       __half* __restrict__ Tl, int N) {
    __shared__ float tb[32][33];
    int k0 = blockIdx.y * 32, n0 = blockIdx.x * 32;
    for (int i = threadIdx.y; i < 32; i += 8)
        tb[i][threadIdx.x] = W[(size_t)(k0 + i) * N + n0 + threadIdx.x];
    __syncthreads();
    for (int i = threadIdx.y; i < 32; i += 8) {
        int n = n0 + i, k = k0 + threadIdx.x;
        float v = tb[threadIdx.x][i];
        __half h = __float2half_rn(v);
        Th[(size_t)n * 256 + k] = h;
        Tl[(size_t)n * 256 + k] = __float2half_rn(v - __half2float(h));
    }
}

// ---------------- init / CSR build ----------------
__global__ void init_attr(const float* __restrict__ na, float* __restrict__ A,
                          __half* __restrict__ Ah, __half* __restrict__ Al) {
    int i = blockIdx.x * blockDim.x + threadIdx.x;
    if (i >= NN * DF) return;
    int r = i >> 8, c = i & 255;
    float v = (c < NF) ? na[r * NF + c] : 0.f;
    A[i] = v;
    __half h = __float2half_rn(v);
    Ah[i] = h;
    Al[i] = __float2half_rn(v - __half2float(h));
}

__global__ void zero_fp(float* __restrict__ fp) {
    int i = blockIdx.x * blockDim.x + threadIdx.x;
    if (i < OF) fp[i] = 0.f;
}

__global__ void zero_deg(int* __restrict__ deg) {
    int i = blockIdx.x * blockDim.x + threadIdx.x;
    if (i <= NN) deg[i] = 0;
}

__global__ void deg_count(const int* __restrict__ dst, int* __restrict__ deg) {
    int e = blockIdx.x * blockDim.x + threadIdx.x;
    if (e < ME) atomicAdd(&deg[dst[e]], 1);
}

// single-block exclusive scan of deg[0..NN) -> offs, cursor
__global__ void scan_deg(const int* __restrict__ deg, int* __restrict__ offs,
                         int* __restrict__ cur) {
    __shared__ int buf[1024];
    __shared__ int carry;
    int tid = threadIdx.x;
    if (tid == 0) carry = 0;
    __syncthreads();
    for (int base = 0; base < NN; base += 1024) {
        int i = base + tid;
        int v = (i < NN) ? deg[i] : 0;
        buf[tid] = v;
        __syncthreads();
        for (int o = 1; o < 1024; o <<= 1) {
            int tv = (tid >= o) ? buf[tid - o] : 0;
            __syncthreads();
            buf[tid] += tv;
            __syncthreads();
        }
        int excl = buf[tid] - v;
        if (i < NN) { offs[i] = carry + excl; cur[i] = carry + excl; }
        __syncthreads();
        if (tid == 1023) carry += buf[1023];
        __syncthreads();
    }
    if (tid == 0) offs[NN] = carry;
}

__global__ void fill_csr(const int* __restrict__ dst, int* __restrict__ cur,
                         int* __restrict__ eidx) {
    int e = blockIdx.x * blockDim.x + threadIdx.x;
    if (e >= ME) return;
    int p = atomicAdd(&cur[dst[e]], 1);
    eidx[p] = e;
}

// warp-per-node: v = A[node] + sum_in-edges (A[src] + [0|EA]); emit hi/lo halves
__global__ __launch_bounds__(256)
void aggregate(const float* __restrict__ A, const float* __restrict__ EA,
               const int* __restrict__ esrc, const int* __restrict__ offs,
               const int* __restrict__ eidx,
               __half* __restrict__ Vh, __half* __restrict__ Vl) {
    int gw = (blockIdx.x * blockDim.x + threadIdx.x) >> 5;
    if (gw >= NN) return;
    int lane = threadIdx.x & 31;
    int c0 = lane * 8;
    float a[8];
    {
        const float4* ar = (const float4*)&A[(size_t)gw * DF + c0];
        float4 x0 = ar[0], x1 = ar[1];
        a[0] = x0.x; a[1] = x0.y; a[2] = x0.z; a[3] = x0.w;
        a[4] = x1.x; a[5] = x1.y; a[6] = x1.z; a[7] = x1.w;
    }
    int beg = offs[gw], end = offs[gw + 1];
    bool ep = (lane >= 24);
#pragma unroll 1
    for (int i = beg; i < end; i++) {
        int e = eidx[i];
        int s = esrc[e];
        const float4* p = (const float4*)&A[(size_t)s * DF + c0];
        float4 b0 = p[0], b1 = p[1];
        a[0] += b0.x; a[1] += b0.y; a[2] += b0.z; a[3] += b0.w;
        a[4] += b1.x; a[5] += b1.y; a[6] += b1.z; a[7] += b1.w;
        if (ep) {
            const float4* q = (const float4*)&EA[(size_t)e * EF + (c0 - NF)];
            float4 e0 = q[0], e1 = q[1];
            a[0] += e0.x; a[1] += e0.y; a[2] += e0.z; a[3] += e0.w;
            a[4] += e1.x; a[5] += e1.y; a[6] += e1.z; a[7] += e1.w;
        }
    }
    __half2 hh[4], ll[4];
#pragma unroll
    for (int j = 0; j < 4; j++) {
        float f0 = a[2 * j], f1 = a[2 * j + 1];
        __half h0 = __float2half_rn(f0), h1 = __float2half_rn(f1);
        hh[j] = __halves2half2(h0, h1);
        ll[j] = __halves2half2(__float2half_rn(f0 - __half2float(h0)),
                               __float2half_rn(f1 - __half2float(h1)));
    }
    *(uint4*)&Vh[(size_t)gw * DF + c0] = *(uint4*)hh;
    *(uint4*)&Vl[(size_t)gw * DF + c0] = *(uint4*)ll;
}

// warp-per-row softmax; per-warp smem accumulator; no block barriers in the row loop
#define SM_SMEM (8 * OF * 4)
__global__ __launch_bounds__(256, 2)
void softmax_warp(const float* __restrict__ L, float* __restrict__ fp, int M) {
    extern __shared__ float sacc[];  // [8][OF]
    int tid = threadIdx.x, lane = tid & 31, w = tid >> 5;
    float* my = sacc + w * OF;
    for (int c = lane; c < OF; c += 32) my[c] = 0.f;
    __syncwarp();
    float4* mp = (float4*)my;
    for (int r = blockIdx.x * 8 + w; r < M; r += gridDim.x * 8) {
        const float4* row = (const float4*)(L + (size_t)r * OF);
        float4 v[16];
        float mx = -1e30f;
#pragma unroll
        for (int j = 0; j < 16; j++) {
            v[j] = row[lane + j * 32];
            mx = fmaxf(mx, fmaxf(fmaxf(v[j].x, v[j].y), fmaxf(v[j].z, v[j].w)));
        }
        for (int o = 16; o; o >>= 1) mx = fmaxf(mx, __shfl_xor_sync(~0u, mx, o));
        float s = 0.f;
#pragma unroll
        for (int j = 0; j < 16; j++) {
            v[j].x = __expf(v[j].x - mx); v[j].y = __expf(v[j].y - mx);
            v[j].z = __expf(v[j].z - mx); v[j].w = __expf(v[j].w - mx);
            s += v[j].x + v[j].y + v[j].z + v[j].w;
        }
        for (int o = 16; o; o >>= 1) s += __shfl_xor_sync(~0u, s, o);
        float inv = 1.f / s;
#pragma unroll
        for (int j = 0; j < 16; j++) {
            float4 acc = mp[lane + j * 32];
            acc.x += v[j].x * inv; acc.y += v[j].y * inv;
            acc.z += v[j].z * inv; acc.w += v[j].w * inv;
            mp[lane + j * 32] = acc;
        }
    }
    __syncthreads();
    for (int c = tid; c < OF; c += 256) {
        float s = 0.f;
#pragma unroll
        for (int w8 = 0; w8 < 8; w8++) s += sacc[w8 * OF + c];
        atomicAdd(&fp[c], s);
    }
}

extern "C" void kernel_launch(void* const* d_in, const int* in_sizes, int n_in,
                              void* d_out, int out_size) {
    const float* node_attr = (const float*)d_in[0];
    const float* edge_attr = (const float*)d_in[1];
    const int*   edge_src  = (const int*)d_in[2];
    const int*   edge_dst  = (const int*)d_in[3];
    const float* W_inner   = (const float*)d_in[4];
    const float* b_inner   = (const float*)d_in[5];
    const float* W_output  = (const float*)d_in[6];
    const float* b_output  = (const float*)d_in[7];
    float* fp = (float*)d_out;

    float *A, *Lb[2];
    __half *Ah, *Al, *Vh, *Vl, *Wth, *Wtl;
    int *deg, *offs, *cur, *eidx;
    cudaGetSymbolAddress((void**)&A, g_A);
    cudaGetSymbolAddress((void**)&Lb[0], g_L0);
    cudaGetSymbolAddress((void**)&Lb[1], g_L1);
    cudaGetSymbolAddress((void**)&Ah, g_Ah);
    cudaGetSymbolAddress((void**)&Al, g_Al);
    cudaGetSymbolAddress((void**)&Vh, g_Vh);
    cudaGetSymbolAddress((void**)&Vl, g_Vl);
    cudaGetSymbolAddress((void**)&Wth, g_Wth);
    cudaGetSymbolAddress((void**)&Wtl, g_Wtl);
    cudaGetSymbolAddress((void**)&deg, g_deg);
    cudaGetSymbolAddress((void**)&offs, g_offs);
    cudaGetSymbolAddress((void**)&cur, g_cur);
    cudaGetSymbolAddress((void**)&eidx, g_eidx);

    static int cfg_done = 0;
    static cudaStream_t s1;
    static cudaEvent_t evStart, evPrep, evL[4], evS[4];
    if (!cfg_done) {
        cudaFuncSetAttribute(gemm_h, cudaFuncAttributeMaxDynamicSharedMemorySize, GH_SMEM);
        cudaFuncSetAttribute(softmax_warp, cudaFuncAttributeMaxDynamicSharedMemorySize, SM_SMEM);
        cudaStreamCreateWithFlags(&s1, cudaStreamNonBlocking);
        cudaEventCreateWithFlags(&evStart, cudaEventDisableTiming);
        cudaEventCreateWithFlags(&evPrep, cudaEventDisableTiming);
        for (int i = 0; i < 4; i++) {
            cudaEventCreateWithFlags(&evL[i], cudaEventDisableTiming);
            cudaEventCreateWithFlags(&evS[i], cudaEventDisableTiming);
        }
        cfg_done = 1;
    }

    dim3 gOut(OF / 128, (NN + 255) / 256);
    dim3 gIn(DF / 128, (NN + 255) / 256);

    // ---- stream 0 (default): critical path; gemm_h is host-launch #3 (ncu -s 5) ----
    wconvT<<<dim3(OF / 32, 8), dim3(32, 8)>>>(W_output, Wth, Wtl, OF);             // 0
    init_attr<<<(NN * DF + 255) / 256, 256>>>(node_attr, A, Ah, Al);               // 1
    zero_fp<<<(OF + 255) / 256, 256>>>(fp);                                        // 2
    cudaEventRecord(evStart, 0);
    gemm_h<<<gOut, 256, GH_SMEM>>>(Ah, Al, Wth, Wtl, b_output, Lb[0], NN, OF,      // 3
                                   nullptr, nullptr, 6 /* K=192: cols 192+ zero */);
    cudaEventRecord(evL[0], 0);

    // ---- stream 1: prep work overlapped with the first big GEMM ----
    cudaStreamWaitEvent(s1, evStart, 0);
    zero_deg<<<(NN + 256) / 256, 256, 0, s1>>>(deg);
    deg_count<<<(ME + 255) / 256, 256, 0, s1>>>(edge_dst, deg);
    scan_deg<<<1, 1024, 0, s1>>>(deg, offs, cur);
    fill_csr<<<(ME + 255) / 256, 256, 0, s1>>>(edge_dst, cur, eidx);
    for (int d = 1; d <= NDEPTH; d++)
        wconvT<<<dim3(OF / 32, 8), dim3(32, 8), 0, s1>>>(
            W_output + (size_t)d * DF * OF,
            Wth + (size_t)d * OF * DF, Wtl + (size_t)d * OF * DF, OF);
    for (int d = 0; d < NDEPTH; d++)
        wconvT<<<dim3(DF / 32, 8), dim3(32, 8), 0, s1>>>(
            W_inner + (size_t)d * DF * DF,
            Wth + WI_OFF + (size_t)d * DF * DF,
            Wtl + WI_OFF + (size_t)d * DF * DF, DF);
    cudaEventRecord(evPrep, s1);
    cudaStreamWaitEvent(0, evPrep, 0);

    for (int d = 0; d < NDEPTH; d++) {
        // stream 1: softmax of depth d, concurrent with stream-0 GEMM chain
        cudaStreamWaitEvent(s1, evL[d], 0);
        softmax_warp<<<296, 256, SM_SMEM, s1>>>(Lb[d & 1], fp, NN);
        cudaEventRecord(evS[d], s1);

        // stream 0: message passing + next logits
        aggregate<<<(NN * 32 + 255) / 256, 256>>>(A, edge_attr, edge_src,
                                                  offs, eidx, Vh, Vl);
        gemm_h<<<gIn, 256, GH_SMEM>>>(Vh, Vl, Wth + WI_OFF + (size_t)d * DF * DF,
                                      Wtl + WI_OFF + (size_t)d * DF * DF,
                                      b_inner + (size_t)d * DF, A, NN, DF, Ah, Al, 8);
        if (d >= 1) cudaStreamWaitEvent(0, evS[d - 1], 0);  // L[(d+1)&1] free?
        gemm_h<<<gOut, 256, GH_SMEM>>>(Ah, Al, Wth + (size_t)(d + 1) * OF * DF,
                                       Wtl + (size_t)(d + 1) * OF * DF,
                                       b_output + (size_t)(d + 1) * OF,
                                       Lb[(d + 1) & 1], NN, OF, nullptr, nullptr, 8);
        cudaEventRecord(evL[d + 1], 0);
    }
    // final softmax on stream 1, then join back to stream 0
    cudaStreamWaitEvent(s1, evL[3], 0);
    softmax_warp<<<296, 256, SM_SMEM, s1>>>(Lb[1], fp, NN);
    cudaEventRecord(evS[3], s1);
    cudaStreamWaitEvent(0, evS[3], 0);
}

// round 15
// speedup vs baseline: 1.0131x; 1.0131x over previous
#include <cuda_runtime.h>
#include <cuda_fp16.h>
#include <cstdint>

#define NN 50000
#define DF 256
#define NF 192
#define EF 64
#define ME 800000
#define OF 2048
#define NDEPTH 3

// static device scratch (no allocations anywhere)
__device__ float g_A[(size_t)NN * DF];
__device__ float g_L0[(size_t)NN * OF];
__device__ float g_L1[(size_t)NN * OF];
__device__ __half g_Ah[(size_t)NN * DF];
__device__ __half g_Al[(size_t)NN * DF];
__device__ __half g_Vh[(size_t)NN * DF];
__device__ __half g_Vl[(size_t)NN * DF];
#define WI_OFF ((size_t)4 * OF * DF)
__device__ __half g_Wth[WI_OFF + (size_t)NDEPTH * DF * DF];
__device__ __half g_Wtl[WI_OFF + (size_t)NDEPTH * DF * DF];
__device__ int g_deg[NN + 1];
__device__ int g_offs[NN + 1];
__device__ int g_cur[NN + 1];
__device__ int g_eidx[ME];

#define SASTR 40  // smem row stride in halfs (80 B): conflict-free frag lds + aligned cp.async

__device__ __forceinline__ uint32_t smem_u32(const void* p) {
    uint32_t a;
    asm("{ .reg .u64 t; cvta.to.shared.u64 t, %1; cvt.u32.u64 %0, t; }" : "=r"(a) : "l"(p));
    return a;
}
__device__ __forceinline__ void cpasync16(uint32_t dst, const void* src, int sz) {
    asm volatile("cp.async.cg.shared.global [%0], [%1], 16, %2;"
                 :: "r"(dst), "l"(src), "r"(sz) : "memory");
}
__device__ __forceinline__ void mma16816(float* c, const uint32_t* a, const uint32_t* b) {
    asm volatile(
        "mma.sync.aligned.m16n8k16.row.col.f32.f16.f16.f32 "
        "{%0,%1,%2,%3}, {%4,%5,%6,%7}, {%8,%9}, {%0,%1,%2,%3};"
        : "+f"(c[0]), "+f"(c[1]), "+f"(c[2]), "+f"(c[3])
        : "r"(a[0]), "r"(a[1]), "r"(a[2]), "r"(a[3]), "r"(b[0]), "r"(b[1]));
}

// CTA tile 256x128, BK=32, 256 threads, 8 warps (4 row x 2 col), warp tile 64x64.
#define STG_B 61440
#define GH_SMEM (2 * STG_B)  // 122880

__global__ __launch_bounds__(256, 1)
void gemm_h(const __half* __restrict__ Ahg, const __half* __restrict__ Alg,
            const __half* __restrict__ Bth, const __half* __restrict__ Btl,
            const float* __restrict__ bias, float* __restrict__ C, int M, int Ng,
            __half* __restrict__ Choh, __half* __restrict__ Chol, int nIter) {
    extern __shared__ __half sm[];
    uint32_t sb = smem_u32(sm);
    int tid = threadIdx.x, lane = tid & 31, wid = tid >> 5;
    int g = lane >> 2, t = lane & 3;
    int wm = (wid & 3) * 64, wn = (wid >> 2) * 64;
    int swp = wid & 1;  // phase stagger: odd warps traverse ks in reverse
    int row0 = blockIdx.y * 256, col0 = blockIdx.x * 128;

    float acc[4][8][4];
#pragma unroll
    for (int i = 0; i < 4; i++)
#pragma unroll
        for (int j = 0; j < 8; j++)
#pragma unroll
            for (int k = 0; k < 4; k++) acc[i][j][k] = 0.f;

    auto issue = [&](int it) {
        int b = it & 1, k0 = it * 32;
        uint32_t bufb = sb + b * STG_B;
#pragma unroll
        for (int q = 0; q < 4; q++) {  // A: 256 rows x 4 chunks, hi+lo
            int idx = tid + q * 256;
            int r = idx >> 2, c4 = idx & 3;
            int rr = row0 + r;
            int p = (rr < M) ? 16 : 0;
            if (rr >= M) rr = M - 1;
            size_t so = (size_t)rr * DF + k0 + c4 * 8;
            uint32_t d = bufb + r * 80 + c4 * 16;
            cpasync16(d, Ahg + so, p);
            cpasync16(d + 20480, Alg + so, p);
        }
#pragma unroll
        for (int q = 0; q < 2; q++) {  // B: 128 rows x 4 chunks, hi+lo
            int idx = tid + q * 256;
            int n = idx >> 2, c4 = idx & 3;
            size_t so = (size_t)(col0 + n) * DF + k0 + c4 * 8;
            uint32_t d = bufb + 40960 + n * 80 + c4 * 16;
            cpasync16(d, Bth + so, 16);
            cpasync16(d + 10240, Btl + so, 16);
        }
        asm volatile("cp.async.commit_group;" ::: "memory");
    };

    auto compute = [&](int b) {
        const __half* Ahs = sm + b * (STG_B / 2);
        const __half* Als = Ahs + 10240;
        const __half* Bhs = Ahs + 20480;
        const __half* Bls = Ahs + 25600;
#pragma unroll
        for (int ks2 = 0; ks2 < 2; ks2++) {
            int ks = ks2 ^ swp;  // half the warps do ks=1 first -> LDS/MMA phases overlap
            uint32_t ah[4][4], al[4][4];
#pragma unroll
            for (int mt = 0; mt < 4; mt++) {
                int r = wm + mt * 16;
                int o0 = (r + g) * SASTR + ks * 16 + 2 * t;
                int o1 = (r + g + 8) * SASTR + ks * 16 + 2 * t;
                ah[mt][0] = *(const uint32_t*)&Ahs[o0];
                ah[mt][1] = *(const uint32_t*)&Ahs[o1];
                ah[mt][2] = *(const uint32_t*)&Ahs[o0 + 8];
                ah[mt][3] = *(const uint32_t*)&Ahs[o1 + 8];
                al[mt][0] = *(const uint32_t*)&Als[o0];
                al[mt][1] = *(const uint32_t*)&Als[o1];
                al[mt][2] = *(const uint32_t*)&Als[o0 + 8];
                al[mt][3] = *(const uint32_t*)&Als[o1 + 8];
            }
            uint32_t bh[8][2], bl[8][2];
#pragma unroll
            for (int nt = 0; nt < 8; nt++) {
                int ob = (wn + nt * 8 + g) * SASTR + ks * 16 + 2 * t;
                bh[nt][0] = *(const uint32_t*)&Bhs[ob];
                bh[nt][1] = *(const uint32_t*)&Bhs[ob + 8];
                bl[nt][0] = *(const uint32_t*)&Bls[ob];
                bl[nt][1] = *(const uint32_t*)&Bls[ob + 8];
            }
#pragma unroll
            for (int nt = 0; nt < 8; nt++)
#pragma unroll
                for (int mt = 0; mt < 4; mt++)
                    mma16816(acc[mt][nt], ah[mt], bh[nt]);  // hi*hi
#pragma unroll
            for (int nt = 0; nt < 8; nt++)
#pragma unroll
                for (int mt = 0; mt < 4; mt++)
                    mma16816(acc[mt][nt], ah[mt], bl[nt]);  // hi*lo
#pragma unroll
            for (int nt = 0; nt < 8; nt++)
#pragma unroll
                for (int mt = 0; mt < 4; mt++)
                    mma16816(acc[mt][nt], al[mt], bh[nt]);  // lo*hi
        }
    };

    issue(0);
#pragma unroll 1
    for (int it = 0; it < nIter; it++) {
        asm volatile("cp.async.wait_group 0;" ::: "memory");
        __syncthreads();
        if (it + 1 < nIter) issue(it + 1);  // overlap next load with this compute
        compute(it & 1);
    }

#pragma unroll
    for (int mt = 0; mt < 4; mt++) {
#pragma unroll
        for (int i = 0; i < 2; i++) {
            int r = row0 + wm + mt * 16 + g + i * 8;
            if (r < M) {
#pragma unroll
                for (int nt = 0; nt < 8; nt++) {
                    int cc = col0 + wn + nt * 8 + 2 * t;
                    float2 v;
                    v.x = acc[mt][nt][i * 2 + 0] + bias[cc];
                    v.y = acc[mt][nt][i * 2 + 1] + bias[cc + 1];
                    *(float2*)&C[(size_t)r * Ng + cc] = v;
                    if (Choh) {
                        __half hx = __float2half_rn(v.x), hy = __float2half_rn(v.y);
                        *(__half2*)&Choh[(size_t)r * Ng + cc] = __halves2half2(hx, hy);
                        *(__half2*)&Chol[(size_t)r * Ng + cc] = __halves2half2(
                            __float2half_rn(v.x - __half2float(hx)),
                            __float2half_rn(v.y - __half2float(hy)));
                    }
                }
            }
        }
    }
}

// W [256, N] -> transposed hi/lo halves Wt[n][k] (K=256 row stride)
__global__ void wconvT(const float* __restrict__ W, __half* __restrict__ Th,
                       __half* __restrict__ Tl, int N) {
    __shared__ float tb[32][33];
    int k0 = blockIdx.y * 32, n0 = blockIdx.x * 32;
    for (int i = threadIdx.y; i < 32; i += 8)
        tb[i][threadIdx.x] = W[(size_t)(k0 + i) * N + n0 + threadIdx.x];
    __syncthreads();
    for (int i = threadIdx.y; i < 32; i += 8) {
        int n = n0 + i, k = k0 + threadIdx.x;
        float v = tb[threadIdx.x][i];
        __half h = __float2half_rn(v);
        Th[(size_t)n * 256 + k] = h;
        Tl[(size_t)n * 256 + k] = __float2half_rn(v - __half2float(h));
    }
}

// ---------------- init / CSR build ----------------
__global__ void init_attr(const float* __restrict__ na, float* __restrict__ A,
                          __half* __restrict__ Ah, __half* __restrict__ Al) {
    int i = blockIdx.x * blockDim.x + threadIdx.x;
    if (i >= NN * DF) return;
    int r = i >> 8, c = i & 255;
    float v = (c < NF) ? na[r * NF + c] : 0.f;
    A[i] = v;
    __half h = __float2half_rn(v);
    Ah[i] = h;
    Al[i] = __float2half_rn(v - __half2float(h));
}

__global__ void zero_fp(float* __restrict__ fp) {
    int i = blockIdx.x * blockDim.x + threadIdx.x;
    if (i < OF) fp[i] = 0.f;
}

__global__ void zero_deg(int* __restrict__ deg) {
    int i = blockIdx.x * blockDim.x + threadIdx.x;
    if (i <= NN) deg[i] = 0;
}

__global__ void deg_count(const int* __restrict__ dst, int* __restrict__ deg) {
    int e = blockIdx.x * blockDim.x + threadIdx.x;
    if (e < ME) atomicAdd(&deg[dst[e]], 1);
}

// single-block exclusive scan of deg[0..NN) -> offs, cursor
__global__ void scan_deg(const int* __restrict__ deg, int* __restrict__ offs,
                         int* __restrict__ cur) {
    __shared__ int buf[1024];
    __shared__ int carry;
    int tid = threadIdx.x;
    if (tid == 0) carry = 0;
    __syncthreads();
    for (int base = 0; base < NN; base += 1024) {
        int i = base + tid;
        int v = (i < NN) ? deg[i] : 0;
        buf[tid] = v;
        __syncthreads();
        for (int o = 1; o < 1024; o <<= 1) {
            int tv = (tid >= o) ? buf[tid - o] : 0;
            __syncthreads();
            buf[tid] += tv;
            __syncthreads();
        }
        int excl = buf[tid] - v;
        if (i < NN) { offs[i] = carry + excl; cur[i] = carry + excl; }
        __syncthreads();
        if (tid == 1023) carry += buf[1023];
        __syncthreads();
    }
    if (tid == 0) offs[NN] = carry;
}

__global__ void fill_csr(const int* __restrict__ dst, int* __restrict__ cur,
                         int* __restrict__ eidx) {
    int e = blockIdx.x * blockDim.x + threadIdx.x;
    if (e >= ME) return;
    int p = atomicAdd(&cur[dst[e]], 1);
    eidx[p] = e;
}

// warp-per-node: v = A[node] + sum_in-edges (A[src] + [0|EA]); emit hi/lo halves
__global__ __launch_bounds__(256)
void aggregate(const float* __restrict__ A, const float* __restrict__ EA,
               const int* __restrict__ esrc, const int* __restrict__ offs,
               const int* __restrict__ eidx,
               __half* __restrict__ Vh, __half* __restrict__ Vl) {
    int gw = (blockIdx.x * blockDim.x + threadIdx.x) >> 5;
    if (gw >= NN) return;
    int lane = threadIdx.x & 31;
    int c0 = lane * 8;
    float a[8];
    {
        const float4* ar = (const float4*)&A[(size_t)gw * DF + c0];
        float4 x0 = ar[0], x1 = ar[1];
        a[0] = x0.x; a[1] = x0.y; a[2] = x0.z; a[3] = x0.w;
        a[4] = x1.x; a[5] = x1.y; a[6] = x1.z; a[7] = x1.w;
    }
    int beg = offs[gw], end = offs[gw + 1];
    bool ep = (lane >= 24);
#pragma unroll 1
    for (int i = beg; i < end; i++) {
        int e = eidx[i];
        int s = esrc[e];
        const float4* p = (const float4*)&A[(size_t)s * DF + c0];
        float4 b0 = p[0], b1 = p[1];
        a[0] += b0.x; a[1] += b0.y; a[2] += b0.z; a[3] += b0.w;
        a[4] += b1.x; a[5] += b1.y; a[6] += b1.z; a[7] += b1.w;
        if (ep) {
            const float4* q = (const float4*)&EA[(size_t)e * EF + (c0 - NF)];
            float4 e0 = q[0], e1 = q[1];
            a[0] += e0.x; a[1] += e0.y; a[2] += e0.z; a[3] += e0.w;
            a[4] += e1.x; a[5] += e1.y; a[6] += e1.z; a[7] += e1.w;
        }
    }
    __half2 hh[4], ll[4];
#pragma unroll
    for (int j = 0; j < 4; j++) {
        float f0 = a[2 * j], f1 = a[2 * j + 1];
        __half h0 = __float2half_rn(f0), h1 = __float2half_rn(f1);
        hh[j] = __halves2half2(h0, h1);
        ll[j] = __halves2half2(__float2half_rn(f0 - __half2float(h0)),
                               __float2half_rn(f1 - __half2float(h1)));
    }
    *(uint4*)&Vh[(size_t)gw * DF + c0] = *(uint4*)hh;
    *(uint4*)&Vl[(size_t)gw * DF + c0] = *(uint4*)ll;
}

// warp-per-row softmax; per-warp smem accumulator; no block barriers in the row loop
#define SM_SMEM (8 * OF * 4)
__global__ __launch_bounds__(256, 2)
void softmax_warp(const float* __restrict__ L, float* __restrict__ fp, int M) {
    extern __shared__ float sacc[];  // [8][OF]
    int tid = threadIdx.x, lane = tid & 31, w = tid >> 5;
    float* my = sacc + w * OF;
    for (int c = lane; c < OF; c += 32) my[c] = 0.f;
    __syncwarp();
    float4* mp = (float4*)my;
    for (int r = blockIdx.x * 8 + w; r < M; r += gridDim.x * 8) {
        const float4* row = (const float4*)(L + (size_t)r * OF);
        float4 v[16];
        float mx = -1e30f;
#pragma unroll
        for (int j = 0; j < 16; j++) {
            v[j] = row[lane + j * 32];
            mx = fmaxf(mx, fmaxf(fmaxf(v[j].x, v[j].y), fmaxf(v[j].z, v[j].w)));
        }
        for (int o = 16; o; o >>= 1) mx = fmaxf(mx, __shfl_xor_sync(~0u, mx, o));
        float s = 0.f;
#pragma unroll
        for (int j = 0; j < 16; j++) {
            v[j].x = __expf(v[j].x - mx); v[j].y = __expf(v[j].y - mx);
            v[j].z = __expf(v[j].z - mx); v[j].w = __expf(v[j].w - mx);
            s += v[j].x + v[j].y + v[j].z + v[j].w;
        }
        for (int o = 16; o; o >>= 1) s += __shfl_xor_sync(~0u, s, o);
        float inv = 1.f / s;
#pragma unroll
        for (int j = 0; j < 16; j++) {
            float4 acc = mp[lane + j * 32];
            acc.x += v[j].x * inv; acc.y += v[j].y * inv;
            acc.z += v[j].z * inv; acc.w += v[j].w * inv;
            mp[lane + j * 32] = acc;
        }
    }
    __syncthreads();
    for (int c = tid; c < OF; c += 256) {
        float s = 0.f;
#pragma unroll
        for (int w8 = 0; w8 < 8; w8++) s += sacc[w8 * OF + c];
        atomicAdd(&fp[c], s);
    }
}

extern "C" void kernel_launch(void* const* d_in, const int* in_sizes, int n_in,
                              void* d_out, int out_size) {
    const float* node_attr = (const float*)d_in[0];
    const float* edge_attr = (const float*)d_in[1];
    const int*   edge_src  = (const int*)d_in[2];
    const int*   edge_dst  = (const int*)d_in[3];
    const float* W_inner   = (const float*)d_in[4];
    const float* b_inner   = (const float*)d_in[5];
    const float* W_output  = (const float*)d_in[6];
    const float* b_output  = (const float*)d_in[7];
    float* fp = (float*)d_out;

    float *A, *Lb[2];
    __half *Ah, *Al, *Vh, *Vl, *Wth, *Wtl;
    int *deg, *offs, *cur, *eidx;
    cudaGetSymbolAddress((void**)&A, g_A);
    cudaGetSymbolAddress((void**)&Lb[0], g_L0);
    cudaGetSymbolAddress((void**)&Lb[1], g_L1);
    cudaGetSymbolAddress((void**)&Ah, g_Ah);
    cudaGetSymbolAddress((void**)&Al, g_Al);
    cudaGetSymbolAddress((void**)&Vh, g_Vh);
    cudaGetSymbolAddress((void**)&Vl, g_Vl);
    cudaGetSymbolAddress((void**)&Wth, g_Wth);
    cudaGetSymbolAddress((void**)&Wtl, g_Wtl);
    cudaGetSymbolAddress((void**)&deg, g_deg);
    cudaGetSymbolAddress((void**)&offs, g_offs);
    cudaGetSymbolAddress((void**)&cur, g_cur);
    cudaGetSymbolAddress((void**)&eidx, g_eidx);

    static int cfg_done = 0;
    static cudaStream_t s1;
    static cudaEvent_t evStart, evPrep, evL[4], evS[4];
    if (!cfg_done) {
        cudaFuncSetAttribute(gemm_h, cudaFuncAttributeMaxDynamicSharedMemorySize, GH_SMEM);
        cudaFuncSetAttribute(softmax_warp, cudaFuncAttributeMaxDynamicSharedMemorySize, SM_SMEM);
        cudaStreamCreateWithFlags(&s1, cudaStreamNonBlocking);
        cudaEventCreateWithFlags(&evStart, cudaEventDisableTiming);
        cudaEventCreateWithFlags(&evPrep, cudaEventDisableTiming);
        for (int i = 0; i < 4; i++) {
            cudaEventCreateWithFlags(&evL[i], cudaEventDisableTiming);
            cudaEventCreateWithFlags(&evS[i], cudaEventDisableTiming);
        }
        cfg_done = 1;
    }

    dim3 gOut(OF / 128, (NN + 255) / 256);
    dim3 gIn(DF / 128, (NN + 255) / 256);

    // ---- stream 0 (default): critical path; gemm_h is host-launch #3 (ncu -s 5) ----
    wconvT<<<dim3(OF / 32, 8), dim3(32, 8)>>>(W_output, Wth, Wtl, OF);             // 0
    init_attr<<<(NN * DF + 255) / 256, 256>>>(node_attr, A, Ah, Al);               // 1
    zero_fp<<<(OF + 255) / 256, 256>>>(fp);                                        // 2
    cudaEventRecord(evStart, 0);
    gemm_h<<<gOut, 256, GH_SMEM>>>(Ah, Al, Wth, Wtl, b_output, Lb[0], NN, OF,      // 3
                                   nullptr, nullptr, 6 /* K=192: cols 192+ zero */);
    cudaEventRecord(evL[0], 0);

    // ---- stream 1: prep work overlapped with the first big GEMM ----
    cudaStreamWaitEvent(s1, evStart, 0);
    zero_deg<<<(NN + 256) / 256, 256, 0, s1>>>(deg);
    deg_count<<<(ME + 255) / 256, 256, 0, s1>>>(edge_dst, deg);
    scan_deg<<<1, 1024, 0, s1>>>(deg, offs, cur);
    fill_csr<<<(ME + 255) / 256, 256, 0, s1>>>(edge_dst, cur, eidx);
    for (int d = 1; d <= NDEPTH; d++)
        wconvT<<<dim3(OF / 32, 8), dim3(32, 8), 0, s1>>>(
            W_output + (size_t)d * DF * OF,
            Wth + (size_t)d * OF * DF, Wtl + (size_t)d * OF * DF, OF);
    for (int d = 0; d < NDEPTH; d++)
        wconvT<<<dim3(DF / 32, 8), dim3(32, 8), 0, s1>>>(
            W_inner + (size_t)d * DF * DF,
            Wth + WI_OFF + (size_t)d * DF * DF,
            Wtl + WI_OFF + (size_t)d * DF * DF, DF);
    cudaEventRecord(evPrep, s1);
    cudaStreamWaitEvent(0, evPrep, 0);

    for (int d = 0; d < NDEPTH; d++) {
        // stream 1: softmax of depth d, concurrent with stream-0 GEMM chain
        cudaStreamWaitEvent(s1, evL[d], 0);
        softmax_warp<<<296, 256, SM_SMEM, s1>>>(Lb[d & 1], fp, NN);
        cudaEventRecord(evS[d], s1);

        // stream 0: message passing + next logits
        aggregate<<<(NN * 32 + 255) / 256, 256>>>(A, edge_attr, edge_src,
                                                  offs, eidx, Vh, Vl);
        gemm_h<<<gIn, 256, GH_SMEM>>>(Vh, Vl, Wth + WI_OFF + (size_t)d * DF * DF,
                                      Wtl + WI_OFF + (size_t)d * DF * DF,
                                      b_inner + (size_t)d * DF, A, NN, DF, Ah, Al, 8);
        if (d >= 1) cudaStreamWaitEvent(0, evS[d - 1], 0);  // L[(d+1)&1] free?
        gemm_h<<<gOut, 256, GH_SMEM>>>(Ah, Al, Wth + (size_t)(d + 1) * OF * DF,
                                       Wtl + (size_t)(d + 1) * OF * DF,
                                       b_output + (size_t)(d + 1) * OF,
                                       Lb[(d + 1) & 1], NN, OF, nullptr, nullptr, 8);
        cudaEventRecord(evL[d + 1], 0);
    }
    // final softmax on stream 1, then join back to stream 0
    cudaStreamWaitEvent(s1, evL[3], 0);
    softmax_warp<<<296, 256, SM_SMEM, s1>>>(Lb[1], fp, NN);
    cudaEventRecord(evS[3], s1);
    cudaStreamWaitEvent(0, evS[3], 0);
}